// round 10
// baseline (speedup 1.0000x reference)
#include <cuda_runtime.h>
#include <cuda_bf16.h>
#include <cstdint>

#define B_N 4096
#define H_N 3
#define K_N 32768
#define D_N 128

#define CAP 256

/* coarse tiling */
#define CBM 256                 /* rows per CTA */
#define CBN 64                  /* codewords per chunk */
#define KSPLIT2 32
#define KN2 (K_N / KSPLIT2)     /* 1024 codewords per CTA */
#define NCH (KN2 / CBN)         /* 16 chunks */

#define APITCH 272              /* bytes per smem row: 256 + 16 pad */
#define BPITCH 272

/* smem layout (bytes) */
#define SM_A       0            /* 256 * 272 = 69632 */
#define SM_B0      69632        /* 64 * 272 = 17408 */
#define SM_B1      87040
#define SM_WNS0    104448       /* 64 floats */
#define SM_WNS1    104704
#define SM_ROWBEST 104960       /* 256 * 4 */
#define SM_TOTAL   105984

// ------------------------------ scratch ------------------------------------
__device__ float           g_resid[B_N * D_N];
__device__ __nv_bfloat16   g_resid16[B_N * D_N];
__device__ __nv_bfloat16   g_emb16[H_N * K_N * D_N];
__device__ float           g_wnorm[H_N * K_N];
__device__ unsigned        g_wnmax[H_N];
__device__ float           g_rnorm[B_N];
__device__ int             g_cand[B_N * CAP];
__device__ int             g_ccnt[B_N];

// ------------------------------ helpers ------------------------------------
__device__ __forceinline__ unsigned f2ord(float f) {
    unsigned u = __float_as_uint(f);
    return (u & 0x80000000u) ? ~u : (u | 0x80000000u);
}
__device__ __forceinline__ float ord2f(unsigned u) {
    return (u & 0x80000000u) ? __uint_as_float(u & 0x7FFFFFFFu)
                             : __uint_as_float(~u);
}
__device__ __forceinline__ uint32_t smem_u32(const void* p) {
    uint32_t a;
    asm("{ .reg .u64 t; cvta.to.shared.u64 t, %1; cvt.u32.u64 %0, t; }"
        : "=r"(a) : "l"(p));
    return a;
}
__device__ __forceinline__ void cp16(uint32_t dst, const void* src) {
    asm volatile("cp.async.ca.shared.global [%0], [%1], 16;"
                 :: "r"(dst), "l"(__cvta_generic_to_global(src)) : "memory");
}
#define CP_COMMIT() asm volatile("cp.async.commit_group;" ::: "memory")
#define CP_WAIT0()  asm volatile("cp.async.wait_group 0;" ::: "memory")

__device__ __forceinline__ void ldmx4(unsigned r[4], uint32_t addr) {
    asm volatile("ldmatrix.sync.aligned.m8n8.x4.shared.b16 {%0,%1,%2,%3}, [%4];"
                 : "=r"(r[0]), "=r"(r[1]), "=r"(r[2]), "=r"(r[3]) : "r"(addr));
}
__device__ __forceinline__ void mma16816(float c[4], const unsigned a[4],
                                         unsigned b0, unsigned b1) {
    asm("mma.sync.aligned.m16n8k16.row.col.f32.bf16.bf16.f32 "
        "{%0,%1,%2,%3},{%4,%5,%6,%7},{%8,%9},{%0,%1,%2,%3};"
        : "+f"(c[0]), "+f"(c[1]), "+f"(c[2]), "+f"(c[3])
        : "r"(a[0]), "r"(a[1]), "r"(a[2]), "r"(a[3]), "r"(b0), "r"(b1));
}

// XLA-GPU-style warp reduction of sum(x^2) over 128 floats (bit-exact w/ ref)
__device__ __forceinline__ float warp_sumsq_128(const float* __restrict__ x, int lane) {
    float acc = 0.f;
    #pragma unroll
    for (int i = 0; i < 4; ++i) {
        float v = x[lane + 32 * i];
        acc = __fadd_rn(acc, __fmul_rn(v, v));
    }
    #pragma unroll
    for (int off = 16; off; off >>= 1)
        acc = __fadd_rn(acc, __shfl_down_sync(0xffffffffu, acc, off));
    return acc;
}

// ---------------------------------------------------------------------------
__global__ void hrq_init_kernel(const float* __restrict__ inp, float* __restrict__ out) {
    int i = blockIdx.x * blockDim.x + threadIdx.x;
    if (i < B_N * D_N) {
        float v = inp[i];
        g_resid[i]   = v;
        g_resid16[i] = __float2bfloat16(v);
        out[B_N + i] = 0.f;
    }
    if (i < B_N) { out[i] = 0.f; g_ccnt[i] = 0; }
    if (i < H_N) g_wnmax[i] = 0u;
}

// emb -> bf16 copy + wnorm (+ per-head max), one warp per codeword
__global__ void hrq_prep_kernel(const float* __restrict__ emb) {
    int gw   = (blockIdx.x * blockDim.x + threadIdx.x) >> 5;
    int lane = threadIdx.x & 31;
    if (gw >= H_N * K_N) return;
    const float* x = emb + (size_t)gw * D_N;
    __nv_bfloat16* y = g_emb16 + (size_t)gw * D_N;
    float acc = 0.f;
    #pragma unroll
    for (int i = 0; i < 4; ++i) {
        float v = x[lane + 32 * i];
        y[lane + 32 * i] = __float2bfloat16(v);
        acc = __fadd_rn(acc, __fmul_rn(v, v));
    }
    #pragma unroll
    for (int off = 16; off; off >>= 1)
        acc = __fadd_rn(acc, __shfl_down_sync(0xffffffffu, acc, off));
    if (lane == 0) {
        g_wnorm[gw] = acc;
        atomicMax(&g_wnmax[gw / K_N], __float_as_uint(acc));
    }
}

__global__ void hrq_rnorm_kernel() {
    int gw   = (blockIdx.x * blockDim.x + threadIdx.x) >> 5;
    int lane = threadIdx.x & 31;
    if (gw >= B_N) return;
    float s = warp_sumsq_128(g_resid + (size_t)gw * D_N, lane);
    if (lane == 0) g_rnorm[gw] = s;
}

// ---------------------------------------------------------------------------
// coarse: bf16 mma.sync, CBM=256 (halves cp.async/LSU traffic per MMA),
// warp tile 64x32, CBN=64 double-buffered. Emits every codeword within delta
// of the (relaxed) running per-row best; delta = 2.5x the hard bf16 rounding
// bound, so the exact winner is always emitted (staleness -> superset).
__global__ void __launch_bounds__(256, 2)
hrq_coarse_kernel(int h) {
    extern __shared__ char smem[];
    const uint32_t sb = smem_u32(smem);
    unsigned* rowbest = (unsigned*)(smem + SM_ROWBEST);

    const int tid  = threadIdx.x;
    const int lane = tid & 31;
    const int wid  = tid >> 5;
    const int wm   = wid & 3;           /* 4 row groups of 64 */
    const int wn   = wid >> 2;          /* 2 col groups of 32 */
    const int g4   = lane >> 2;         /* 0..7 */
    const int q4   = lane & 3;

    const int rowBase = blockIdx.x * CBM;
    const int kBase   = blockIdx.y * KN2;

    rowbest[tid] = 0u;                  /* 256 entries, 256 threads */

    const __nv_bfloat16* Wh = g_emb16 + ((size_t)h * K_N + kBase) * D_N;
    const float* hwg        = g_wnorm + (size_t)h * K_N + kBase;

    // stage A (256x128 bf16 -> padded smem rows), once per block
    {
        const char* src = (const char*)(g_resid16 + (size_t)rowBase * D_N);
        #pragma unroll
        for (int j = 0; j < 16; ++j) {
            int i = tid + 256 * j, row = i >> 4, c = i & 15;
            cp16(sb + SM_A + row * APITCH + c * 16, src + i * 16);
        }
    }
    // stage B chunk 0 + wns0
    {
        const char* src = (const char*)Wh;
        #pragma unroll
        for (int j = 0; j < 4; ++j) {
            int i = tid + 256 * j, row = i >> 4, c = i & 15;
            cp16(sb + SM_B0 + row * BPITCH + c * 16, src + i * 16);
        }
        if (tid < 16) cp16(sb + SM_WNS0 + tid * 16, (const char*)hwg + tid * 16);
    }
    CP_COMMIT();

    // per-thread deltas (8 result rows per thread: 4 m-tiles x 2 sub-rows)
    float delta[8];
    {
        float wnmax = __uint_as_float(g_wnmax[h]);
        #pragma unroll
        for (int mt = 0; mt < 4; ++mt)
            #pragma unroll
            for (int hi = 0; hi < 2; ++hi) {
                int rr = mt * 2 + hi;
                float R = g_rnorm[rowBase + wm * 64 + mt * 16 + hi * 8 + g4];
                delta[rr] = 0.02f * sqrtf(R * wnmax);
            }
    }
    CP_WAIT0();
    __syncthreads();

    // ldmatrix lane-address components
    const int aRow = lane & 15;
    const int aCol = (lane >> 4) << 3;                    /* 0 or 8 */
    const int bN   = ((lane >= 16) ? 8 : 0) + (lane & 7);
    const int bK   = ((lane >> 3) & 1) << 3;

    for (int ch = 0; ch < NCH; ++ch) {
        const int cur = ch & 1;
        if (ch + 1 < NCH) {   // prefetch next B chunk into the other buffer
            const char* src = (const char*)(Wh + (size_t)(ch + 1) * CBN * D_N);
            uint32_t bdst = sb + (cur ? SM_B0 : SM_B1);
            #pragma unroll
            for (int j = 0; j < 4; ++j) {
                int i = tid + 256 * j, row = i >> 4, c = i & 15;
                cp16(bdst + row * BPITCH + c * 16, src + i * 16);
            }
            if (tid < 16)
                cp16(sb + (cur ? SM_WNS0 : SM_WNS1) + tid * 16,
                     (const char*)(hwg + (ch + 1) * CBN) + tid * 16);
            CP_COMMIT();
        }

        const uint32_t abase = sb + SM_A;
        const uint32_t bbase = sb + (cur ? SM_B1 : SM_B0);
        const float* wns = (const float*)(smem + (cur ? SM_WNS1 : SM_WNS0));

        float acc[4][4][4];
        #pragma unroll
        for (int mt = 0; mt < 4; ++mt)
            #pragma unroll
            for (int nt = 0; nt < 4; ++nt)
                #pragma unroll
                for (int c = 0; c < 4; ++c) acc[mt][nt][c] = 0.f;

        #pragma unroll
        for (int kt = 0; kt < 8; ++kt) {
            unsigned af[4][4], bf[2][4];
            #pragma unroll
            for (int mt = 0; mt < 4; ++mt)
                ldmx4(af[mt], abase + (wm * 64 + mt * 16 + aRow) * APITCH
                              + (kt * 16 + aCol) * 2);
            #pragma unroll
            for (int p = 0; p < 2; ++p)
                ldmx4(bf[p], bbase + (wn * 32 + p * 16 + bN) * BPITCH
                             + (kt * 16 + bK) * 2);
            #pragma unroll
            for (int mt = 0; mt < 4; ++mt)
                #pragma unroll
                for (int nt = 0; nt < 4; ++nt)
                    mma16816(acc[mt][nt], af[mt],
                             bf[nt >> 1][(nt & 1) * 2],
                             bf[nt >> 1][(nt & 1) * 2 + 1]);
        }

        // per-row maxes of s = 2*acc - wn
        float mx[8];
        #pragma unroll
        for (int rr = 0; rr < 8; ++rr) mx[rr] = -3.4e38f;
        #pragma unroll
        for (int mt = 0; mt < 4; ++mt)
            #pragma unroll
            for (int nt = 0; nt < 4; ++nt)
                #pragma unroll
                for (int c = 0; c < 4; ++c) {
                    int col = nt * 8 + 2 * q4 + (c & 1);
                    float s = fmaf(2.f, acc[mt][nt][c], -wns[wn * 32 + col]);
                    int rr = mt * 2 + (c >> 1);
                    if (s > mx[rr]) mx[rr] = s;
                }
        #pragma unroll
        for (int mt = 0; mt < 4; ++mt)
            #pragma unroll
            for (int hi = 0; hi < 2; ++hi)
                atomicMax(&rowbest[wm * 64 + mt * 16 + hi * 8 + g4],
                          f2ord(mx[mt * 2 + hi]));

        // relaxed threshold read (includes own update; staleness -> superset)
        int kc = kBase + ch * CBN + wn * 32;
        #pragma unroll
        for (int mt = 0; mt < 4; ++mt)
            #pragma unroll
            for (int hi = 0; hi < 2; ++hi) {
                int rr = mt * 2 + hi;
                int rl = wm * 64 + mt * 16 + hi * 8 + g4;
                float thr = ord2f(rowbest[rl]) - delta[rr];
                if (mx[rr] < thr) continue;            /* fast skip */
                int row = rowBase + rl;
                #pragma unroll
                for (int nt = 0; nt < 4; ++nt)
                    #pragma unroll
                    for (int lo = 0; lo < 2; ++lo) {
                        int c = hi * 2 + lo;
                        int col = nt * 8 + 2 * q4 + lo;
                        float s = fmaf(2.f, acc[mt][nt][c], -wns[wn * 32 + col]);
                        if (s >= thr) {
                            int idx = atomicAdd(&g_ccnt[row], 1);
                            if (idx < CAP) g_cand[row * CAP + idx] = kc + col;
                        }
                    }
            }

        if (ch + 1 < NCH) CP_WAIT0();
        __syncthreads();
    }
}

// ---------------------------------------------------------------------------
// rescore (bit-exact reference arithmetic) + update, fused.
__global__ void hrq_rescore_update_kernel(const float* __restrict__ emb,
                                          float* __restrict__ out, int h) {
    __shared__ float rs[D_N];
    __shared__ unsigned long long wkey[4];
    __shared__ int swin;

    int b = blockIdx.x;
    int t = threadIdx.x;          // 128 threads
    int lane = t & 31, w = t >> 5;

    rs[t] = g_resid[(size_t)b * D_N + t];
    __syncthreads();

    int n = g_ccnt[b]; if (n > CAP) n = CAP; if (n < 1) n = 1;
    float R = g_rnorm[b];
    const float* __restrict__ Wh = emb + (size_t)h * K_N * D_N;
    const float* __restrict__ hw = g_wnorm + (size_t)h * K_N;

    unsigned long long best = 0ull;
    for (int i = t; i < n; i += 128) {
        int k = g_cand[b * CAP + i];
        const float4* wrow = (const float4*)(Wh + (size_t)k * D_N);
        float acc = 0.f;
        #pragma unroll
        for (int d4 = 0; d4 < D_N / 4; ++d4) {   // sequential ascending d
            float4 wv = __ldg(wrow + d4);
            acc = fmaf(rs[4 * d4],     wv.x, acc);
            acc = fmaf(rs[4 * d4 + 1], wv.y, acc);
            acc = fmaf(rs[4 * d4 + 2], wv.z, acc);
            acc = fmaf(rs[4 * d4 + 3], wv.w, acc);
        }
        float tt = __fsub_rn(__fadd_rn(R, hw[k]), 2.0f * acc);
        unsigned long long key =
            ((unsigned long long)f2ord(-tt) << 32) |
            (unsigned long long)(0xFFFFFFFFu - (unsigned)k);
        if (key > best) best = key;
    }
    #pragma unroll
    for (int off = 16; off; off >>= 1) {
        unsigned long long o = __shfl_xor_sync(0xffffffffu, best, off);
        if (o > best) best = o;
    }
    if (lane == 0) wkey[w] = best;
    __syncthreads();
    if (t == 0) {
        unsigned long long m = wkey[0];
        for (int i = 1; i < 4; ++i) if (wkey[i] > m) m = wkey[i];
        swin = (int)(0xFFFFFFFFu - (unsigned)(m & 0xFFFFFFFFull));
    }
    __syncthreads();

    int k = swin;
    float q  = Wh[(size_t)k * D_N + t];
    float nr = g_resid[(size_t)b * D_N + t] - q;
    g_resid[(size_t)b * D_N + t]   = nr;
    g_resid16[(size_t)b * D_N + t] = __float2bfloat16(nr);
    out[B_N + b * D_N + t] += q;
    __syncthreads();
    if (t < 32) {
        float s = warp_sumsq_128(g_resid + (size_t)b * D_N, t);
        if (t == 0) {
            g_rnorm[b] = s;
            out[B_N + B_N * D_N + b * H_N + h] = (float)k;
            g_ccnt[b] = 0;
        }
    }
}

// ---------------------------------------------------------------------------
extern "C" void kernel_launch(void* const* d_in, const int* in_sizes, int n_in,
                              void* d_out, int out_size) {
    const float* inputs = (const float*)d_in[0];
    const float* emb    = (const float*)d_in[1];
    if (n_in >= 2 && in_sizes[0] != B_N * D_N) {
        inputs = (const float*)d_in[1];
        emb    = (const float*)d_in[0];
    }
    float* out = (float*)d_out;

    cudaFuncSetAttribute(hrq_coarse_kernel,
                         cudaFuncAttributeMaxDynamicSharedMemorySize, SM_TOTAL);

    hrq_init_kernel<<<(B_N * D_N + 255) / 256, 256>>>(inputs, out);
    hrq_prep_kernel<<<(H_N * K_N * 32 + 255) / 256, 256>>>(emb);
    hrq_rnorm_kernel<<<(B_N * 32 + 255) / 256, 256>>>();

    dim3 cgrid(B_N / CBM, KSPLIT2);
    for (int h = 0; h < H_N; ++h) {
        hrq_coarse_kernel<<<cgrid, 256, SM_TOTAL>>>(h);
        hrq_rescore_update_kernel<<<B_N, 128>>>(emb, out, h);
    }
}

// round 11
// speedup vs baseline: 1.2399x; 1.2399x over previous
#include <cuda_runtime.h>
#include <cuda_bf16.h>
#include <cstdint>

#define B_N 4096
#define H_N 3
#define K_N 32768
#define D_N 128

#define CAP 256

/* coarse tiling — R6 geometry (proven), occupancy 3 */
#define CBM 128                 /* rows per CTA */
#define CBN 64                  /* codewords per chunk */
#define KSPLIT2 16
#define KN2 (K_N / KSPLIT2)     /* 2048 codewords per CTA */
#define NCH (KN2 / CBN)         /* 32 chunks */

#define APITCH 272              /* bytes per smem row: 256 + 16 pad */
#define BPITCH 272

/* smem layout (bytes) */
#define SM_A       0            /* 128 * 272 = 34816 */
#define SM_B0      34816        /* 64 * 272 = 17408 */
#define SM_B1      52224
#define SM_WNS0    69632        /* 64 floats */
#define SM_WNS1    69888
#define SM_ROWBEST 70144        /* 128 * 4 */
#define SM_TOTAL   70656        /* x3 CTAs = 212KB <= 227KB */

// ------------------------------ scratch ------------------------------------
__device__ float           g_resid[B_N * D_N];
__device__ __nv_bfloat16   g_resid16[B_N * D_N];
__device__ __nv_bfloat16   g_emb16[H_N * K_N * D_N];
__device__ float           g_wnorm[H_N * K_N];
__device__ unsigned        g_wnmax[H_N];
__device__ float           g_rnorm[B_N];
__device__ int             g_cand[B_N * CAP];
__device__ int             g_ccnt[B_N];

// ------------------------------ helpers ------------------------------------
__device__ __forceinline__ unsigned f2ord(float f) {
    unsigned u = __float_as_uint(f);
    return (u & 0x80000000u) ? ~u : (u | 0x80000000u);
}
__device__ __forceinline__ float ord2f(unsigned u) {
    return (u & 0x80000000u) ? __uint_as_float(u & 0x7FFFFFFFu)
                             : __uint_as_float(~u);
}
__device__ __forceinline__ uint32_t smem_u32(const void* p) {
    uint32_t a;
    asm("{ .reg .u64 t; cvta.to.shared.u64 t, %1; cvt.u32.u64 %0, t; }"
        : "=r"(a) : "l"(p));
    return a;
}
__device__ __forceinline__ void cp16(uint32_t dst, const void* src) {
    asm volatile("cp.async.ca.shared.global [%0], [%1], 16;"
                 :: "r"(dst), "l"(__cvta_generic_to_global(src)) : "memory");
}
#define CP_COMMIT() asm volatile("cp.async.commit_group;" ::: "memory")
#define CP_WAIT0()  asm volatile("cp.async.wait_group 0;" ::: "memory")

__device__ __forceinline__ void ldmx4(unsigned r[4], uint32_t addr) {
    asm volatile("ldmatrix.sync.aligned.m8n8.x4.shared.b16 {%0,%1,%2,%3}, [%4];"
                 : "=r"(r[0]), "=r"(r[1]), "=r"(r[2]), "=r"(r[3]) : "r"(addr));
}
__device__ __forceinline__ void mma16816(float c[4], const unsigned a[4],
                                         unsigned b0, unsigned b1) {
    asm("mma.sync.aligned.m16n8k16.row.col.f32.bf16.bf16.f32 "
        "{%0,%1,%2,%3},{%4,%5,%6,%7},{%8,%9},{%0,%1,%2,%3};"
        : "+f"(c[0]), "+f"(c[1]), "+f"(c[2]), "+f"(c[3])
        : "r"(a[0]), "r"(a[1]), "r"(a[2]), "r"(a[3]), "r"(b0), "r"(b1));
}

// XLA-GPU-style warp reduction of sum(x^2) over 128 floats (bit-exact w/ ref)
__device__ __forceinline__ float warp_sumsq_128(const float* __restrict__ x, int lane) {
    float acc = 0.f;
    #pragma unroll
    for (int i = 0; i < 4; ++i) {
        float v = x[lane + 32 * i];
        acc = __fadd_rn(acc, __fmul_rn(v, v));
    }
    #pragma unroll
    for (int off = 16; off; off >>= 1)
        acc = __fadd_rn(acc, __shfl_down_sync(0xffffffffu, acc, off));
    return acc;
}

// ---------------------------------------------------------------------------
__global__ void hrq_init_kernel(const float* __restrict__ inp, float* __restrict__ out) {
    int i = blockIdx.x * blockDim.x + threadIdx.x;
    if (i < B_N * D_N) {
        float v = inp[i];
        g_resid[i]   = v;
        g_resid16[i] = __float2bfloat16(v);
        out[B_N + i] = 0.f;
    }
    if (i < B_N) { out[i] = 0.f; g_ccnt[i] = 0; }
    if (i < H_N) g_wnmax[i] = 0u;
}

// emb -> bf16 copy + wnorm (+ per-head max), one warp per codeword
__global__ void hrq_prep_kernel(const float* __restrict__ emb) {
    int gw   = (blockIdx.x * blockDim.x + threadIdx.x) >> 5;
    int lane = threadIdx.x & 31;
    if (gw >= H_N * K_N) return;
    const float* x = emb + (size_t)gw * D_N;
    __nv_bfloat16* y = g_emb16 + (size_t)gw * D_N;
    float acc = 0.f;
    #pragma unroll
    for (int i = 0; i < 4; ++i) {
        float v = x[lane + 32 * i];
        y[lane + 32 * i] = __float2bfloat16(v);
        acc = __fadd_rn(acc, __fmul_rn(v, v));
    }
    #pragma unroll
    for (int off = 16; off; off >>= 1)
        acc = __fadd_rn(acc, __shfl_down_sync(0xffffffffu, acc, off));
    if (lane == 0) {
        g_wnorm[gw] = acc;
        atomicMax(&g_wnmax[gw / K_N], __float_as_uint(acc));
    }
}

__global__ void hrq_rnorm_kernel() {
    int gw   = (blockIdx.x * blockDim.x + threadIdx.x) >> 5;
    int lane = threadIdx.x & 31;
    if (gw >= B_N) return;
    float s = warp_sumsq_128(g_resid + (size_t)gw * D_N, lane);
    if (lane == 0) g_rnorm[gw] = s;
}

// ---------------------------------------------------------------------------
// coarse: bf16 mma.sync via ldmatrix + cp.async double-buffered B,
// 3 CTAs/SM for latency hiding. Emits every codeword within delta of the
// (relaxed) running per-row best; delta = 2.5x the hard bf16 rounding bound,
// so the exact winner is always emitted (staleness -> superset).
__global__ void __launch_bounds__(256, 3)
hrq_coarse_kernel(int h) {
    extern __shared__ char smem[];
    const uint32_t sb = smem_u32(smem);
    unsigned* rowbest = (unsigned*)(smem + SM_ROWBEST);

    const int tid  = threadIdx.x;
    const int lane = tid & 31;
    const int wid  = tid >> 5;
    const int wm   = wid & 3;           /* 4 row groups of 32 */
    const int wn   = wid >> 2;          /* 2 col groups of 32 */
    const int g4   = lane >> 2;         /* 0..7 */
    const int q4   = lane & 3;

    const int rowBase = blockIdx.x * CBM;
    const int kBase   = blockIdx.y * KN2;

    if (tid < 128) rowbest[tid] = 0u;

    const __nv_bfloat16* Wh = g_emb16 + ((size_t)h * K_N + kBase) * D_N;
    const float* hwg        = g_wnorm + (size_t)h * K_N + kBase;

    // stage A (128x128 bf16 -> padded smem rows)
    {
        const char* src = (const char*)(g_resid16 + (size_t)rowBase * D_N);
        #pragma unroll
        for (int j = 0; j < 8; ++j) {
            int i = tid + 256 * j, row = i >> 4, c = i & 15;
            cp16(sb + SM_A + row * APITCH + c * 16, src + i * 16);
        }
    }
    // stage B chunk 0 + wns0
    {
        const char* src = (const char*)Wh;
        #pragma unroll
        for (int j = 0; j < 4; ++j) {
            int i = tid + 256 * j, row = i >> 4, c = i & 15;
            cp16(sb + SM_B0 + row * BPITCH + c * 16, src + i * 16);
        }
        if (tid < 16) cp16(sb + SM_WNS0 + tid * 16, (const char*)hwg + tid * 16);
    }
    CP_COMMIT();

    // per-thread rows & deltas (4 result rows per thread)
    int rloc[4];
    float delta[4];
    {
        float wnmax = __uint_as_float(g_wnmax[h]);
        #pragma unroll
        for (int mt = 0; mt < 2; ++mt)
            #pragma unroll
            for (int hi = 0; hi < 2; ++hi) {
                int rr = mt * 2 + hi;
                rloc[rr] = wm * 32 + mt * 16 + hi * 8 + g4;
                float R = g_rnorm[rowBase + rloc[rr]];
                delta[rr] = 0.02f * sqrtf(R * wnmax);
            }
    }
    CP_WAIT0();
    __syncthreads();

    // ldmatrix lane-address components
    const int aRow = lane & 15;
    const int aCol = (lane >> 4) << 3;                    /* 0 or 8 */
    const int bN   = ((lane >= 16) ? 8 : 0) + (lane & 7);
    const int bK   = ((lane >> 3) & 1) << 3;

    for (int ch = 0; ch < NCH; ++ch) {
        const int cur = ch & 1;
        if (ch + 1 < NCH) {   // prefetch next B chunk into the other buffer
            const char* src = (const char*)(Wh + (size_t)(ch + 1) * CBN * D_N);
            uint32_t bdst = sb + (cur ? SM_B0 : SM_B1);
            #pragma unroll
            for (int j = 0; j < 4; ++j) {
                int i = tid + 256 * j, row = i >> 4, c = i & 15;
                cp16(bdst + row * BPITCH + c * 16, src + i * 16);
            }
            if (tid < 16)
                cp16(sb + (cur ? SM_WNS0 : SM_WNS1) + tid * 16,
                     (const char*)(hwg + (ch + 1) * CBN) + tid * 16);
            CP_COMMIT();
        }

        const uint32_t abase = sb + SM_A;
        const uint32_t bbase = sb + (cur ? SM_B1 : SM_B0);
        const float* wns = (const float*)(smem + (cur ? SM_WNS1 : SM_WNS0));

        float acc[2][4][4];
        #pragma unroll
        for (int mt = 0; mt < 2; ++mt)
            #pragma unroll
            for (int nt = 0; nt < 4; ++nt)
                #pragma unroll
                for (int c = 0; c < 4; ++c) acc[mt][nt][c] = 0.f;

        #pragma unroll
        for (int kt = 0; kt < 8; ++kt) {
            unsigned a0[4], a1[4], b01[4], b23[4];
            ldmx4(a0, abase + (wm * 32 +      aRow) * APITCH + (kt * 16 + aCol) * 2);
            ldmx4(a1, abase + (wm * 32 + 16 + aRow) * APITCH + (kt * 16 + aCol) * 2);
            ldmx4(b01, bbase + (wn * 32 +      bN) * BPITCH + (kt * 16 + bK) * 2);
            ldmx4(b23, bbase + (wn * 32 + 16 + bN) * BPITCH + (kt * 16 + bK) * 2);
            mma16816(acc[0][0], a0, b01[0], b01[1]);
            mma16816(acc[0][1], a0, b01[2], b01[3]);
            mma16816(acc[0][2], a0, b23[0], b23[1]);
            mma16816(acc[0][3], a0, b23[2], b23[3]);
            mma16816(acc[1][0], a1, b01[0], b01[1]);
            mma16816(acc[1][1], a1, b01[2], b01[3]);
            mma16816(acc[1][2], a1, b23[0], b23[1]);
            mma16816(acc[1][3], a1, b23[2], b23[3]);
        }

        // per-row maxes of s = 2*acc - wn
        float mx[4] = { -3.4e38f, -3.4e38f, -3.4e38f, -3.4e38f };
        #pragma unroll
        for (int mt = 0; mt < 2; ++mt)
            #pragma unroll
            for (int nt = 0; nt < 4; ++nt)
                #pragma unroll
                for (int c = 0; c < 4; ++c) {
                    int col = nt * 8 + 2 * q4 + (c & 1);  /* local in wn group */
                    float s = fmaf(2.f, acc[mt][nt][c], -wns[wn * 32 + col]);
                    int rr = mt * 2 + (c >> 1);
                    if (s > mx[rr]) mx[rr] = s;
                }
        #pragma unroll
        for (int rr = 0; rr < 4; ++rr)
            atomicMax(&rowbest[rloc[rr]], f2ord(mx[rr]));

        // relaxed threshold read (includes own update; staleness -> superset)
        int kc = kBase + ch * CBN + wn * 32;
        #pragma unroll
        for (int mt = 0; mt < 2; ++mt)
            #pragma unroll
            for (int hi = 0; hi < 2; ++hi) {
                int rr = mt * 2 + hi;
                float thr = ord2f(rowbest[rloc[rr]]) - delta[rr];
                if (mx[rr] < thr) continue;            /* fast skip */
                int row = rowBase + rloc[rr];
                #pragma unroll
                for (int nt = 0; nt < 4; ++nt)
                    #pragma unroll
                    for (int lo = 0; lo < 2; ++lo) {
                        int c = hi * 2 + lo;
                        int col = nt * 8 + 2 * q4 + lo;
                        float s = fmaf(2.f, acc[mt][nt][c], -wns[wn * 32 + col]);
                        if (s >= thr) {
                            int idx = atomicAdd(&g_ccnt[row], 1);
                            if (idx < CAP) g_cand[row * CAP + idx] = kc + col;
                        }
                    }
            }

        if (ch + 1 < NCH) CP_WAIT0();
        __syncthreads();
    }
}

// ---------------------------------------------------------------------------
// rescore (bit-exact reference arithmetic) + update, fused.
__global__ void hrq_rescore_update_kernel(const float* __restrict__ emb,
                                          float* __restrict__ out, int h) {
    __shared__ float rs[D_N];
    __shared__ unsigned long long wkey[4];
    __shared__ int swin;

    int b = blockIdx.x;
    int t = threadIdx.x;          // 128 threads
    int lane = t & 31, w = t >> 5;

    rs[t] = g_resid[(size_t)b * D_N + t];
    __syncthreads();

    int n = g_ccnt[b]; if (n > CAP) n = CAP; if (n < 1) n = 1;
    float R = g_rnorm[b];
    const float* __restrict__ Wh = emb + (size_t)h * K_N * D_N;
    const float* __restrict__ hw = g_wnorm + (size_t)h * K_N;

    unsigned long long best = 0ull;
    for (int i = t; i < n; i += 128) {
        int k = g_cand[b * CAP + i];
        const float4* wrow = (const float4*)(Wh + (size_t)k * D_N);
        float acc = 0.f;
        #pragma unroll
        for (int d4 = 0; d4 < D_N / 4; ++d4) {   // sequential ascending d
            float4 wv = __ldg(wrow + d4);
            acc = fmaf(rs[4 * d4],     wv.x, acc);
            acc = fmaf(rs[4 * d4 + 1], wv.y, acc);
            acc = fmaf(rs[4 * d4 + 2], wv.z, acc);
            acc = fmaf(rs[4 * d4 + 3], wv.w, acc);
        }
        float tt = __fsub_rn(__fadd_rn(R, hw[k]), 2.0f * acc);
        unsigned long long key =
            ((unsigned long long)f2ord(-tt) << 32) |
            (unsigned long long)(0xFFFFFFFFu - (unsigned)k);
        if (key > best) best = key;
    }
    #pragma unroll
    for (int off = 16; off; off >>= 1) {
        unsigned long long o = __shfl_xor_sync(0xffffffffu, best, off);
        if (o > best) best = o;
    }
    if (lane == 0) wkey[w] = best;
    __syncthreads();
    if (t == 0) {
        unsigned long long m = wkey[0];
        for (int i = 1; i < 4; ++i) if (wkey[i] > m) m = wkey[i];
        swin = (int)(0xFFFFFFFFu - (unsigned)(m & 0xFFFFFFFFull));
    }
    __syncthreads();

    int k = swin;
    float q  = Wh[(size_t)k * D_N + t];
    float nr = g_resid[(size_t)b * D_N + t] - q;
    g_resid[(size_t)b * D_N + t]   = nr;
    g_resid16[(size_t)b * D_N + t] = __float2bfloat16(nr);
    out[B_N + b * D_N + t] += q;
    __syncthreads();
    if (t < 32) {
        float s = warp_sumsq_128(g_resid + (size_t)b * D_N, t);
        if (t == 0) {
            g_rnorm[b] = s;
            out[B_N + B_N * D_N + b * H_N + h] = (float)k;
            g_ccnt[b] = 0;
        }
    }
}

// ---------------------------------------------------------------------------
extern "C" void kernel_launch(void* const* d_in, const int* in_sizes, int n_in,
                              void* d_out, int out_size) {
    const float* inputs = (const float*)d_in[0];
    const float* emb    = (const float*)d_in[1];
    if (n_in >= 2 && in_sizes[0] != B_N * D_N) {
        inputs = (const float*)d_in[1];
        emb    = (const float*)d_in[0];
    }
    float* out = (float*)d_out;

    cudaFuncSetAttribute(hrq_coarse_kernel,
                         cudaFuncAttributeMaxDynamicSharedMemorySize, SM_TOTAL);

    hrq_init_kernel<<<(B_N * D_N + 255) / 256, 256>>>(inputs, out);
    hrq_prep_kernel<<<(H_N * K_N * 32 + 255) / 256, 256>>>(emb);
    hrq_rnorm_kernel<<<(B_N * 32 + 255) / 256, 256>>>();

    dim3 cgrid(B_N / CBM, KSPLIT2);
    for (int h = 0; h < H_N; ++h) {
        hrq_coarse_kernel<<<cgrid, 256, SM_TOTAL>>>(h);
        hrq_rescore_update_kernel<<<B_N, 128>>>(emb, out, h);
    }
}